// round 15
// baseline (speedup 1.0000x reference)
#include <cuda_runtime.h>
#include <cuda_fp16.h>
#include <cstdint>

#define N_NODES 100000
#define N_EDGES 1600000
#define N_GRAPHS 512
#define HID 128
#define NCAT 10
#define NT_ROWS 258      // NODE_TYPE_BUCKETS + 2
#define ID_ROWS 50002    // IDENT_BUCKETS + 2
#define E_PAD (N_EDGES + 8 * N_NODES)   // padded edge-list capacity

// ---------------- scratch (device globals; no runtime allocation) ----------------
__device__ __align__(16) float  g_TNs[NT_ROWS * HID];
__device__ __align__(16) float  g_TNn[NT_ROWS * HID];
__device__ __align__(16) __half g_TIs[ID_ROWS * HID];        // fp16 ident tables
__device__ __align__(16) __half g_TIn[ID_ROWS * HID];
__device__ __align__(16) float  g_self0[N_NODES * HID];      // x0 @ Ws0 (no bias)
__device__ __align__(16) __half g_y0h[(N_NODES + 1) * HID];  // +1 dummy zero row
// combined GEMM A: row=node, cols 0-127 = h1 (fp16), cols 128-255 = invdeg*agg(h1)
__device__ __align__(16) __half g_a1h[(N_NODES + 1) * 256];  // +1 dummy zero row
__device__ __align__(16) __half g_w1hi[256 * 128];           // [Ws1; Wn1] fp16 hi
__device__ __align__(16) __half g_w1lo[256 * 128];           // residual lo
__device__ int   g_deg[N_NODES];
__device__ int   g_off[N_NODES];        // block-local padded offsets
__device__ int   g_cursor[N_NODES];
__device__ int   g_bsum[512];
__device__ int   g_ssrc[E_PAD];         // src ids sorted by dst, segments padded to 8
__device__ float g_invdeg[N_NODES];
__device__ int   g_depthmax;
__device__ __align__(16) float g_pooled[N_GRAPHS * HID];
__device__ float g_cnt[N_GRAPHS];

// ---------------- helpers --------------------------------------------------------
__device__ __forceinline__ unsigned long long dup2(float a) {
    unsigned long long r;
    asm("mov.b64 %0, {%1, %1};" : "=l"(r) : "f"(a));
    return r;
}
__device__ __forceinline__ void fma2(unsigned long long& acc, unsigned long long a,
                                     unsigned long long b) {
    asm("fma.rn.f32x2 %0, %1, %2, %0;" : "+l"(acc) : "l"(a), "l"(b));
}
__device__ __forceinline__ void unpack2(unsigned long long v, float& lo, float& hi) {
    asm("mov.b64 {%0, %1}, %2;" : "=f"(lo), "=f"(hi) : "l"(v));
}
__device__ __forceinline__ float4 ld4(const float* p) {
    return *reinterpret_cast<const float4*>(p);
}
__device__ __forceinline__ void add4(float4& a, float4 b) {
    a.x += b.x; a.y += b.y; a.z += b.z; a.w += b.w;
}
__device__ __forceinline__ void fma4(float4& a, float s, float4 b) {
    a.x += s * b.x; a.y += s * b.y; a.z += s * b.z; a.w += s * b.w;
}
__device__ __forceinline__ void red2(const float* p, float x, float y) {
    asm volatile("red.global.add.v2.f32 [%0], {%1,%2};"
                 :: "l"(p), "f"(x), "f"(y) : "memory");
}
__device__ __forceinline__ void haccu(float4& a, uint2 u) {
    __half2 h0 = *reinterpret_cast<const __half2*>(&u.x);
    __half2 h1 = *reinterpret_cast<const __half2*>(&u.y);
    float2 f0 = __half22float2(h0);
    float2 f1 = __half22float2(h1);
    a.x += f0.x; a.y += f0.y; a.z += f1.x; a.w += f1.y;
}
__device__ __forceinline__ uint32_t h2bits(__half2 h) {
    return *reinterpret_cast<const uint32_t*>(&h);
}
__device__ __forceinline__ void st4h(__half* p, float4 v) {
    __half2 h0 = __floats2half2_rn(v.x, v.y);
    __half2 h1 = __floats2half2_rn(v.z, v.w);
    uint2 u;
    u.x = h2bits(h0); u.y = h2bits(h1);
    *reinterpret_cast<uint2*>(p) = u;
}
__device__ __forceinline__ uint32_t smem_u32(const void* p) {
    uint32_t a;
    asm("{ .reg .u64 t; cvta.to.shared.u64 t, %1; cvt.u32.u64 %0, t; }" : "=r"(a) : "l"(p));
    return a;
}
#define LDSM4(r0, r1, r2, r3, addr)                                             \
    asm volatile("ldmatrix.sync.aligned.m8n8.x4.shared.b16 {%0,%1,%2,%3}, [%4];" \
                 : "=r"(r0), "=r"(r1), "=r"(r2), "=r"(r3) : "r"(addr))
#define LDSM4T(r0, r1, r2, r3, addr)                                                  \
    asm volatile("ldmatrix.sync.aligned.m8n8.x4.trans.shared.b16 {%0,%1,%2,%3}, [%4];" \
                 : "=r"(r0), "=r"(r1), "=r"(r2), "=r"(r3) : "r"(addr))
#define MMA16816(d, a, b0, b1)                                                     \
    asm volatile(                                                                  \
        "mma.sync.aligned.m16n8k16.row.col.f32.f16.f16.f32 "                       \
        "{%0,%1,%2,%3}, {%4,%5,%6,%7}, {%8,%9}, {%0,%1,%2,%3};"                    \
        : "+f"((d)[0]), "+f"((d)[1]), "+f"((d)[2]), "+f"((d)[3])                   \
        : "r"((a)[0]), "r"((a)[1]), "r"((a)[2]), "r"((a)[3]), "r"(b0), "r"(b1))

// ---------------- K1: zero/init small state ---------------------------------------
__global__ void k_zero() {
    int tid = blockIdx.x * blockDim.x + threadIdx.x;
    int stride = gridDim.x * blockDim.x;
    for (int i = tid; i < N_NODES; i += stride) { g_deg[i] = 0; g_cursor[i] = 0; }
    for (int i = tid; i < N_GRAPHS * HID; i += stride) g_pooled[i] = 0.f;
    for (int i = tid; i < N_GRAPHS; i += stride) g_cnt[i] = 0.f;
    // dummy zero rows gathered by pad slots
    for (int i = tid; i < HID / 2; i += stride)
        reinterpret_cast<uint32_t*>(g_y0h + N_NODES * HID)[i] = 0u;
    for (int i = tid; i < 256 / 2; i += stride)
        reinterpret_cast<uint32_t*>(g_a1h + N_NODES * 256)[i] = 0u;
    if (tid == 0) g_depthmax = 0;
}

// ---------------- K2: degrees (int4 edges), depth max, graph counts ---------------
__global__ void k_stats(const int* __restrict__ edge, const int* __restrict__ depth,
                        const int* __restrict__ batch) {
    int tid = blockIdx.x * blockDim.x + threadIdx.x;
    int stride = gridDim.x * blockDim.x;
    const int4* dst4 = reinterpret_cast<const int4*>(edge + N_EDGES);
    for (int q = tid; q < N_EDGES / 4; q += stride) {
        int4 d = __ldg(&dst4[q]);
        atomicAdd(&g_deg[d.x], 1);
        atomicAdd(&g_deg[d.y], 1);
        atomicAdd(&g_deg[d.z], 1);
        atomicAdd(&g_deg[d.w], 1);
    }
    int dm = 0;
    for (int i = tid; i < N_NODES; i += stride) dm = max(dm, depth[i]);
    dm = __reduce_max_sync(0xffffffffu, dm);
    if ((threadIdx.x & 31) == 0) atomicMax(&g_depthmax, dm);
    for (int i = tid; i < N_NODES; i += stride)
        atomicAdd(&g_cnt[batch[i]], 1.0f);
}

// ---------------- K3a/b: two-level exclusive scan of PADDED degrees ---------------
__global__ void k_scan1() {
    __shared__ int ws[8];
    int b = blockIdx.x, tid = threadIdx.x;
    int lane = tid & 31, wid = tid >> 5;
    int i = b * 256 + tid;
    int v = (i < N_NODES) ? ((g_deg[i] + 7) & ~7) : 0;   // pad to multiple of 8
    int x = v;
#pragma unroll
    for (int o = 1; o < 32; o <<= 1) {
        int y = __shfl_up_sync(0xffffffffu, x, o);
        if (lane >= o) x += y;
    }
    if (lane == 31) ws[wid] = x;
    __syncthreads();
    if (tid < 8) {
        int s = ws[tid];
#pragma unroll
        for (int o = 1; o < 8; o <<= 1) {
            int y = __shfl_up_sync(0xffu, s, o);
            if ((tid & 7) >= o) s += y;
        }
        ws[tid] = s;
    }
    __syncthreads();
    int pre = (wid > 0) ? ws[wid - 1] : 0;
    if (i < N_NODES) g_off[i] = pre + x - v;
    if (tid == 255) g_bsum[b] = pre + x;
}
__global__ void k_scan2() {
    __shared__ int ws[16];
    int tid = threadIdx.x;
    int lane = tid & 31, wid = tid >> 5;
    int v = g_bsum[tid];
    int x = v;
#pragma unroll
    for (int o = 1; o < 32; o <<= 1) {
        int y = __shfl_up_sync(0xffffffffu, x, o);
        if (lane >= o) x += y;
    }
    if (lane == 31) ws[wid] = x;
    __syncthreads();
    if (tid < 16) {
        int s = ws[tid];
#pragma unroll
        for (int o = 1; o < 16; o <<= 1) {
            int y = __shfl_up_sync(0xffffu, s, o);
            if ((tid & 15) >= o) s += y;
        }
        ws[tid] = s;
    }
    __syncthreads();
    int pre = (wid > 0) ? ws[wid - 1] : 0;
    g_bsum[tid] = pre + x - v;
}
// final padded offset of node d = g_off[d] + g_bsum[d >> 8]

// ---------------- K4: pad-fill + bucket edges by destination ----------------------
__global__ void k_sortedges(const int* __restrict__ edge) {
    int tid = blockIdx.x * blockDim.x + threadIdx.x;
    int stride = gridDim.x * blockDim.x;
    for (int d = tid; d < N_NODES; d += stride) {
        int deg = g_deg[d];
        int pdeg = (deg + 7) & ~7;
        int beg = g_off[d] + g_bsum[d >> 8];
        for (int k = deg; k < pdeg; k++) g_ssrc[beg + k] = N_NODES;
    }
    const int4* src4 = reinterpret_cast<const int4*>(edge);
    const int4* dst4 = reinterpret_cast<const int4*>(edge + N_EDGES);
    for (int q = tid; q < N_EDGES / 4; q += stride) {
        int4 s = __ldg(&src4[q]);
        int4 d = __ldg(&dst4[q]);
        int p;
        p = atomicAdd(&g_cursor[d.x], 1);
        g_ssrc[g_off[d.x] + g_bsum[d.x >> 8] + p] = s.x;
        p = atomicAdd(&g_cursor[d.y], 1);
        g_ssrc[g_off[d.y] + g_bsum[d.y >> 8] + p] = s.y;
        p = atomicAdd(&g_cursor[d.z], 1);
        g_ssrc[g_off[d.z] + g_bsum[d.z >> 8] + p] = s.z;
        p = atomicAdd(&g_cursor[d.w], 1);
        g_ssrc[g_off[d.w] + g_bsum[d.w >> 8] + p] = s.w;
    }
}

// ---------------- K5: ident embedding tables (fp16 output) ------------------------
__global__ __launch_bounds__(256) void k_table_id(const float* __restrict__ embi,
                                                  const float* __restrict__ Ws0,
                                                  const float* __restrict__ Wn0) {
    __shared__ float sW[32][128];
    __shared__ float nW[32][128];
    int tid = threadIdx.x;
    for (int i = tid; i < 32 * 128; i += 256) {
        int k = i >> 7, n = i & 127;
        sW[k][n] = Ws0[(64 + k) * 128 + n];
        nW[k][n] = Wn0[(64 + k) * 128 + n];
    }
    __syncthreads();
    int lane = tid & 31;
    int gw = (blockIdx.x * 256 + tid) >> 5;
    int nwarps = (gridDim.x * 256) >> 5;
    for (int r = gw; r < ID_ROWS; r += nwarps) {
        float me = embi[r * 32 + lane];
        unsigned long long as0 = 0, as1 = 0, an0 = 0, an1 = 0;
#pragma unroll
        for (int k = 0; k < 32; k++) {
            float e = __shfl_sync(0xffffffffu, me, k);
            unsigned long long e2 = dup2(e);
            const unsigned long long* ps =
                reinterpret_cast<const unsigned long long*>(&sW[k][lane * 4]);
            const unsigned long long* pn =
                reinterpret_cast<const unsigned long long*>(&nW[k][lane * 4]);
            fma2(as0, e2, ps[0]); fma2(as1, e2, ps[1]);
            fma2(an0, e2, pn[0]); fma2(an1, e2, pn[1]);
        }
        float v0, v1, v2, v3;
        unpack2(as0, v0, v1); unpack2(as1, v2, v3);
        st4h(g_TIs + r * 128 + lane * 4, make_float4(v0, v1, v2, v3));
        unpack2(an0, v0, v1); unpack2(an1, v2, v3);
        st4h(g_TIn + r * 128 + lane * 4, make_float4(v0, v1, v2, v3));
    }
}

// ---------------- K6: node-type tables + weight hi/lo split (fused) ---------------
__global__ void k_table_node(const float* __restrict__ embn,
                             const float* __restrict__ Ws0,
                             const float* __restrict__ Wn0,
                             const float* __restrict__ Ws1,
                             const float* __restrict__ Wn1) {
    int tid = threadIdx.x;
    if (blockIdx.x < 128) {   // weight split part
        int i = blockIdx.x * 256 + tid;
        int r = i >> 7, n = i & 127;
        float v = (r < 128) ? Ws1[r * 128 + n] : Wn1[(r - 128) * 128 + n];
        __half hi = __float2half_rn(v);
        g_w1hi[i] = hi;
        g_w1lo[i] = __float2half_rn(v - __half2float(hi));
        return;
    }
    int lane = tid & 31;
    int gw = ((blockIdx.x - 128) * 256 + tid) >> 5;
    int nwarps = ((gridDim.x - 128) * 256) >> 5;
    for (int r = gw; r < NT_ROWS; r += nwarps) {
        float me0 = embn[r * 64 + lane];
        float me1 = embn[r * 64 + 32 + lane];
        float4 as = make_float4(0, 0, 0, 0), an = make_float4(0, 0, 0, 0);
#pragma unroll
        for (int k = 0; k < 64; k++) {
            float e = (k < 32) ? __shfl_sync(0xffffffffu, me0, k)
                               : __shfl_sync(0xffffffffu, me1, k - 32);
            float4 ws = ld4(Ws0 + k * 128 + lane * 4);
            float4 wn = ld4(Wn0 + k * 128 + lane * 4);
            fma4(as, e, ws);
            fma4(an, e, wn);
        }
        *reinterpret_cast<float4*>(g_TNs + r * 128 + lane * 4) = as;
        *reinterpret_cast<float4*>(g_TNn + r * 128 + lane * 4) = an;
    }
}

// ---------------- K7: per-node transformed features -------------------------------
__global__ void k_nodefeat(const int* __restrict__ nt, const int* __restrict__ ih,
                           const float* __restrict__ flags, const int* __restrict__ depth,
                           const float* __restrict__ Ws0, const float* __restrict__ Wn0) {
    int tid = threadIdx.x;
    int lane = tid & 31;
    int gw = (blockIdx.x * 256 + tid) >> 5;
    int nwarps = (gridDim.x * 256) >> 5;
    float inv_dmax = 1.0f / fmaxf((float)g_depthmax, 1.0f);
    int c4 = lane * 4;
    for (int i = gw; i < N_NODES; i += nwarps) {
        int t = nt[i], id = ih[i];
        float4 s = ld4(g_TNs + t * 128 + c4);
        haccu(s, *reinterpret_cast<const uint2*>(g_TIs + id * 128 + c4));
        float4 y = ld4(g_TNn + t * 128 + c4);
        haccu(y, *reinterpret_cast<const uint2*>(g_TIn + id * 128 + c4));
        float dn = (float)depth[i] * inv_dmax;
#pragma unroll
        for (int j = 0; j < 5; j++) {
            float f = __ldg(&flags[i * 5 + j]);
            fma4(s, f, ld4(Ws0 + (96 + j) * 128 + c4));
            fma4(y, f, ld4(Wn0 + (96 + j) * 128 + c4));
        }
        fma4(s, dn, ld4(Ws0 + 101 * 128 + c4));
        fma4(y, dn, ld4(Wn0 + 101 * 128 + c4));
        *reinterpret_cast<float4*>(g_self0 + i * 128 + c4) = s;
        st4h(g_y0h + i * 128 + c4, y);
        if (lane == 0) g_invdeg[i] = 1.0f / fmaxf((float)g_deg[i], 1.0f);
    }
}

// ---------------- K8: layer-0 aggregation (1 warp per CTA; pipelined) -------------
__global__ __launch_bounds__(32) void k_agg0(const float* __restrict__ b1,
                                             const float* __restrict__ b2) {
    int lane = threadIdx.x;
    int d = blockIdx.x;
    int c4 = lane * 4;
    int beg = g_off[d] + g_bsum[d >> 8];
    int end = beg + ((g_deg[d] + 7) & ~7);
    float4 a0 = make_float4(0, 0, 0, 0), a1 = a0, a2 = a0, a3 = a0;
    int l8 = lane & 7;
    int sv = (beg < end) ? __ldg(&g_ssrc[beg + l8]) : 0;
    for (int k = beg; k < end; k += 8) {
        int svn = (k + 8 < end) ? __ldg(&g_ssrc[k + 8 + l8]) : 0;
        int s[8];
#pragma unroll
        for (int j = 0; j < 8; j++) s[j] = __shfl_sync(0xffffffffu, sv, j);
        uint2 u[8];
#pragma unroll
        for (int j = 0; j < 8; j++)
            u[j] = *reinterpret_cast<const uint2*>(g_y0h + s[j] * 128 + c4);
        haccu(a0, u[0]); haccu(a1, u[1]); haccu(a2, u[2]); haccu(a3, u[3]);
        haccu(a0, u[4]); haccu(a1, u[5]); haccu(a2, u[6]); haccu(a3, u[7]);
        sv = svn;
    }
    add4(a0, a1); add4(a2, a3); add4(a0, a2);
    float inv = g_invdeg[d];
    float4 v = ld4(g_self0 + d * 128 + c4);
    fma4(v, inv, a0);
    float4 bias1 = __ldg(reinterpret_cast<const float4*>(b1 + c4));
    float4 bias2 = __ldg(reinterpret_cast<const float4*>(b2 + c4));
    v.x = fmaxf(v.x + bias1.x + bias2.x, 0.f);
    v.y = fmaxf(v.y + bias1.y + bias2.y, 0.f);
    v.z = fmaxf(v.z + bias1.z + bias2.z, 0.f);
    v.w = fmaxf(v.w + bias1.w + bias2.w, 0.f);
    st4h(g_a1h + d * 256 + c4, v);
}

// ---------------- K9: layer-1 aggregation (1 warp per CTA; pipelined) -------------
__global__ __launch_bounds__(32) void k_agg1() {
    int lane = threadIdx.x;
    int d = blockIdx.x;
    int c4 = lane * 4;
    int beg = g_off[d] + g_bsum[d >> 8];
    int end = beg + ((g_deg[d] + 7) & ~7);
    float4 a0 = make_float4(0, 0, 0, 0), a1 = a0, a2 = a0, a3 = a0;
    int l8 = lane & 7;
    int sv = (beg < end) ? __ldg(&g_ssrc[beg + l8]) : 0;
    for (int k = beg; k < end; k += 8) {
        int svn = (k + 8 < end) ? __ldg(&g_ssrc[k + 8 + l8]) : 0;
        int s[8];
#pragma unroll
        for (int j = 0; j < 8; j++) s[j] = __shfl_sync(0xffffffffu, sv, j);
        uint2 u[8];
#pragma unroll
        for (int j = 0; j < 8; j++)
            u[j] = *reinterpret_cast<const uint2*>(g_a1h + s[j] * 256 + c4);
        haccu(a0, u[0]); haccu(a1, u[1]); haccu(a2, u[2]); haccu(a3, u[3]);
        haccu(a0, u[4]); haccu(a1, u[5]); haccu(a2, u[6]); haccu(a3, u[7]);
        sv = svn;
    }
    add4(a0, a1); add4(a2, a3); add4(a0, a2);
    float inv = g_invdeg[d];
    a0.x *= inv; a0.y *= inv; a0.z *= inv; a0.w *= inv;
    st4h(g_a1h + d * 256 + 128 + c4, a0);
}

// ---------------- K10: tensor-core GEMM (B hi/lo split) + bias + relu + pool ------
__global__ __launch_bounds__(256) void k_gemm_h(const float* __restrict__ bs,
                                                const float* __restrict__ bn,
                                                const int* __restrict__ batch) {
    __shared__ __half As[128][48];   // 96B rows (16B-aligned)
    __shared__ __half Bh[32][136];   // 272B rows (16B-aligned)
    __shared__ __half Bl[32][136];
    int tid = threadIdx.x;
    int lane = tid & 31, wid = tid >> 5;
    int wm = wid & 3;
    int wn = wid >> 2;
    int m0 = blockIdx.x * 128;

    float acc[2][8][4];
#pragma unroll
    for (int mi = 0; mi < 2; mi++)
#pragma unroll
        for (int ni = 0; ni < 8; ni++)
#pragma unroll
            for (int q = 0; q < 4; q++) acc[mi][ni][q] = 0.f;

    uint32_t sA = smem_u32(As), sBh = smem_u32(Bh), sBl = smem_u32(Bl);

    for (int kt = 0; kt < 8; kt++) {
        int kk = kt * 32;
#pragma unroll
        for (int i = 0; i < 2; i++) {
            int idx = tid + i * 256;
            int row = idx >> 2, seg = idx & 3;
            uint4 v = make_uint4(0, 0, 0, 0);
            int grow = m0 + row;
            if (grow < N_NODES)
                v = *reinterpret_cast<const uint4*>(g_a1h + grow * 256 + kk + seg * 8);
            *reinterpret_cast<uint4*>(&As[row][seg * 8]) = v;
        }
#pragma unroll
        for (int i = 0; i < 2; i++) {
            int idx = tid + i * 256;
            int row = idx >> 4, seg = idx & 15;
            *reinterpret_cast<uint4*>(&Bh[row][seg * 8]) =
                *reinterpret_cast<const uint4*>(g_w1hi + (kk + row) * 128 + seg * 8);
            *reinterpret_cast<uint4*>(&Bl[row][seg * 8]) =
                *reinterpret_cast<const uint4*>(g_w1lo + (kk + row) * 128 + seg * 8);
        }
        __syncthreads();
#pragma unroll
        for (int ks = 0; ks < 32; ks += 16) {
            uint32_t afr[2][4];
#pragma unroll
            for (int mi = 0; mi < 2; mi++) {
                uint32_t addr = sA + ((wm * 32 + mi * 16 + (lane & 15)) * 48 +
                                      ks + ((lane >> 4) << 3)) * 2;
                LDSM4(afr[mi][0], afr[mi][1], afr[mi][2], afr[mi][3], addr);
            }
            uint32_t bh[8][2], bl[8][2];
#pragma unroll
            for (int nq = 0; nq < 4; nq++) {
                uint32_t off = ((ks + (lane & 7) + ((lane >> 3) & 1) * 8) * 136 +
                                wn * 64 + nq * 16 + ((lane >> 4) & 1) * 8) * 2;
                LDSM4T(bh[nq * 2][0], bh[nq * 2][1], bh[nq * 2 + 1][0],
                       bh[nq * 2 + 1][1], sBh + off);
                LDSM4T(bl[nq * 2][0], bl[nq * 2][1], bl[nq * 2 + 1][0],
                       bl[nq * 2 + 1][1], sBl + off);
            }
#pragma unroll
            for (int mi = 0; mi < 2; mi++)
#pragma unroll
                for (int ni = 0; ni < 8; ni++) {
                    MMA16816(acc[mi][ni], afr[mi], bh[ni][0], bh[ni][1]);
                    MMA16816(acc[mi][ni], afr[mi], bl[ni][0], bl[ni][1]);
                }
        }
        __syncthreads();
    }

    // epilogue: bias + relu + red into pooled
    int tg = lane & 3, rg = lane >> 2;
#pragma unroll
    for (int mi = 0; mi < 2; mi++) {
        int r0 = m0 + wm * 32 + mi * 16 + rg;
        int r1 = r0 + 8;
        int bi0 = (r0 < N_NODES) ? __ldg(&batch[r0]) : -1;
        int bi1 = (r1 < N_NODES) ? __ldg(&batch[r1]) : -1;
#pragma unroll
        for (int ni = 0; ni < 8; ni++) {
            int c = wn * 64 + ni * 8 + tg * 2;
            float bb0 = __ldg(&bs[c]) + __ldg(&bn[c]);
            float bb1 = __ldg(&bs[c + 1]) + __ldg(&bn[c + 1]);
            float* ac = acc[mi][ni];
            if (bi0 >= 0)
                red2(g_pooled + bi0 * 128 + c,
                     fmaxf(ac[0] + bb0, 0.f), fmaxf(ac[1] + bb1, 0.f));
            if (bi1 >= 0)
                red2(g_pooled + bi1 * 128 + c,
                     fmaxf(ac[2] + bb0, 0.f), fmaxf(ac[3] + bb1, 0.f));
        }
    }
}

// ---------------- K11: heads ------------------------------------------------------
__global__ void k_heads(const float* __restrict__ Wr, const float* __restrict__ br,
                        const float* __restrict__ Wc, const float* __restrict__ bc,
                        float* __restrict__ out) {
    int g = blockIdx.x;
    int lane = threadIdx.x;
    float inv = 1.0f / fmaxf(g_cnt[g], 1.0f);
    float4 gv = *reinterpret_cast<const float4*>(g_pooled + g * HID + lane * 4);
    float gvals[4] = {gv.x * inv, gv.y * inv, gv.z * inv, gv.w * inv};

    float pr = 0.f;
#pragma unroll
    for (int i = 0; i < 4; i++) pr += gvals[i] * Wr[lane * 4 + i];
#pragma unroll
    for (int off = 16; off > 0; off >>= 1) pr += __shfl_xor_sync(0xffffffffu, pr, off);
    if (lane == 0) out[g] = pr + br[0];

    for (int o = 0; o < NCAT; o++) {
        float p = 0.f;
#pragma unroll
        for (int i = 0; i < 4; i++) p += gvals[i] * Wc[(lane * 4 + i) * NCAT + o];
#pragma unroll
        for (int off = 16; off > 0; off >>= 1) p += __shfl_xor_sync(0xffffffffu, p, off);
        if (lane == 0) out[N_GRAPHS + g * NCAT + o] = p + bc[o];
    }
}

// ---------------- launch (single stream) ------------------------------------------
extern "C" void kernel_launch(void* const* d_in, const int* in_sizes, int n_in,
                              void* d_out, int out_size) {
    const int*   node_type = (const int*)d_in[0];
    const int*   ident     = (const int*)d_in[1];
    const float* flags     = (const float*)d_in[2];
    const int*   depth     = (const int*)d_in[3];
    const int*   edge      = (const int*)d_in[4];
    const int*   batch     = (const int*)d_in[5];
    const float* emb_node  = (const float*)d_in[6];
    const float* emb_ident = (const float*)d_in[7];
    const float* Ws0 = (const float*)d_in[8];
    const float* bs0 = (const float*)d_in[9];
    const float* Wn0 = (const float*)d_in[10];
    const float* bn0 = (const float*)d_in[11];
    const float* Ws1 = (const float*)d_in[12];
    const float* bs1 = (const float*)d_in[13];
    const float* Wn1 = (const float*)d_in[14];
    const float* bn1 = (const float*)d_in[15];
    const float* Wr  = (const float*)d_in[16];
    const float* br  = (const float*)d_in[17];
    const float* Wc  = (const float*)d_in[18];
    const float* bc  = (const float*)d_in[19];
    float* out = (float*)d_out;

    k_zero<<<1024, 256>>>();
    k_stats<<<2048, 256>>>(edge, depth, batch);
    k_scan1<<<(N_NODES + 255) / 256, 256>>>();
    k_scan2<<<1, 512>>>();
    k_sortedges<<<2048, 256>>>(edge);
    k_table_id<<<2048, 256>>>(emb_ident, Ws0, Wn0);
    k_table_node<<<128 + 33, 256>>>(emb_node, Ws0, Wn0, Ws1, Wn1);
    k_nodefeat<<<2048, 256>>>(node_type, ident, flags, depth, Ws0, Wn0);
    k_agg0<<<N_NODES, 32>>>(bs0, bn0);
    k_agg1<<<N_NODES, 32>>>();
    k_gemm_h<<<(N_NODES + 127) / 128, 256>>>(bs1, bn1, batch);
    k_heads<<<N_GRAPHS, 32>>>(Wr, br, Wc, bc, out);
}

// round 16
// speedup vs baseline: 1.0394x; 1.0394x over previous
#include <cuda_runtime.h>
#include <cuda_fp16.h>
#include <cstdint>

#define N_NODES 100000
#define N_EDGES 1600000
#define N_GRAPHS 512
#define HID 128
#define NCAT 10
#define NT_ROWS 258      // NODE_TYPE_BUCKETS + 2
#define ID_ROWS 50002    // IDENT_BUCKETS + 2
#define E_PAD (N_EDGES + 8 * N_NODES)   // padded edge-list capacity

// ---------------- scratch (device globals; no runtime allocation) ----------------
__device__ __align__(16) float  g_TNs[NT_ROWS * HID];
__device__ __align__(16) float  g_TNn[NT_ROWS * HID];
__device__ __align__(16) __half g_TIs[ID_ROWS * HID];        // fp16 ident tables
__device__ __align__(16) __half g_TIn[ID_ROWS * HID];
__device__ __align__(16) __half g_self0h[N_NODES * HID];     // x0 @ Ws0 (fp16)
__device__ __align__(16) __half g_y0h[(N_NODES + 1) * HID];  // +1 dummy zero row
// combined GEMM A: row=node, cols 0-127 = h1 (fp16), cols 128-255 = invdeg*agg(h1)
__device__ __align__(16) __half g_a1h[(N_NODES + 1) * 256];  // +1 dummy zero row
__device__ __align__(16) __half g_w1hi[256 * 128];           // [Ws1; Wn1] fp16 hi
__device__ __align__(16) __half g_w1lo[256 * 128];           // residual lo
__device__ int   g_deg[N_NODES];
__device__ int   g_off[N_NODES];        // block-local padded offsets
__device__ int   g_cursor[N_NODES];
__device__ int   g_bsum[512];
__device__ int   g_ssrc[E_PAD];         // src ids sorted by dst, segments padded to 8
__device__ float g_invdeg[N_NODES];
__device__ int   g_depthmax;
__device__ __align__(16) float g_pooled[N_GRAPHS * HID];
__device__ float g_cnt[N_GRAPHS];

// ---------------- helpers --------------------------------------------------------
__device__ __forceinline__ unsigned long long dup2(float a) {
    unsigned long long r;
    asm("mov.b64 %0, {%1, %1};" : "=l"(r) : "f"(a));
    return r;
}
__device__ __forceinline__ void fma2(unsigned long long& acc, unsigned long long a,
                                     unsigned long long b) {
    asm("fma.rn.f32x2 %0, %1, %2, %0;" : "+l"(acc) : "l"(a), "l"(b));
}
__device__ __forceinline__ void unpack2(unsigned long long v, float& lo, float& hi) {
    asm("mov.b64 {%0, %1}, %2;" : "=f"(lo), "=f"(hi) : "l"(v));
}
__device__ __forceinline__ float4 ld4(const float* p) {
    return *reinterpret_cast<const float4*>(p);
}
__device__ __forceinline__ void add4(float4& a, float4 b) {
    a.x += b.x; a.y += b.y; a.z += b.z; a.w += b.w;
}
__device__ __forceinline__ void fma4(float4& a, float s, float4 b) {
    a.x += s * b.x; a.y += s * b.y; a.z += s * b.z; a.w += s * b.w;
}
__device__ __forceinline__ void red2(const float* p, float x, float y) {
    asm volatile("red.global.add.v2.f32 [%0], {%1,%2};"
                 :: "l"(p), "f"(x), "f"(y) : "memory");
}
__device__ __forceinline__ void haccu(float4& a, uint2 u) {
    __half2 h0 = *reinterpret_cast<const __half2*>(&u.x);
    __half2 h1 = *reinterpret_cast<const __half2*>(&u.y);
    float2 f0 = __half22float2(h0);
    float2 f1 = __half22float2(h1);
    a.x += f0.x; a.y += f0.y; a.z += f1.x; a.w += f1.y;
}
__device__ __forceinline__ float4 h2f4(uint2 u) {
    __half2 h0 = *reinterpret_cast<const __half2*>(&u.x);
    __half2 h1 = *reinterpret_cast<const __half2*>(&u.y);
    float2 f0 = __half22float2(h0);
    float2 f1 = __half22float2(h1);
    return make_float4(f0.x, f0.y, f1.x, f1.y);
}
__device__ __forceinline__ uint32_t h2bits(__half2 h) {
    return *reinterpret_cast<const uint32_t*>(&h);
}
__device__ __forceinline__ void st4h(__half* p, float4 v) {
    __half2 h0 = __floats2half2_rn(v.x, v.y);
    __half2 h1 = __floats2half2_rn(v.z, v.w);
    uint2 u;
    u.x = h2bits(h0); u.y = h2bits(h1);
    *reinterpret_cast<uint2*>(p) = u;
}
__device__ __forceinline__ uint32_t smem_u32(const void* p) {
    uint32_t a;
    asm("{ .reg .u64 t; cvta.to.shared.u64 t, %1; cvt.u32.u64 %0, t; }" : "=r"(a) : "l"(p));
    return a;
}
#define LDSM4(r0, r1, r2, r3, addr)                                             \
    asm volatile("ldmatrix.sync.aligned.m8n8.x4.shared.b16 {%0,%1,%2,%3}, [%4];" \
                 : "=r"(r0), "=r"(r1), "=r"(r2), "=r"(r3) : "r"(addr))
#define LDSM4T(r0, r1, r2, r3, addr)                                                  \
    asm volatile("ldmatrix.sync.aligned.m8n8.x4.trans.shared.b16 {%0,%1,%2,%3}, [%4];" \
                 : "=r"(r0), "=r"(r1), "=r"(r2), "=r"(r3) : "r"(addr))
#define MMA16816(d, a, b0, b1)                                                     \
    asm volatile(                                                                  \
        "mma.sync.aligned.m16n8k16.row.col.f32.f16.f16.f32 "                       \
        "{%0,%1,%2,%3}, {%4,%5,%6,%7}, {%8,%9}, {%0,%1,%2,%3};"                    \
        : "+f"((d)[0]), "+f"((d)[1]), "+f"((d)[2]), "+f"((d)[3])                   \
        : "r"((a)[0]), "r"((a)[1]), "r"((a)[2]), "r"((a)[3]), "r"(b0), "r"(b1))

// ---------------- K1: zero/init small state ---------------------------------------
__global__ void k_zero() {
    int tid = blockIdx.x * blockDim.x + threadIdx.x;
    int stride = gridDim.x * blockDim.x;
    for (int i = tid; i < N_NODES; i += stride) { g_deg[i] = 0; g_cursor[i] = 0; }
    for (int i = tid; i < N_GRAPHS * HID; i += stride) g_pooled[i] = 0.f;
    for (int i = tid; i < N_GRAPHS; i += stride) g_cnt[i] = 0.f;
    // dummy zero rows gathered by pad slots
    for (int i = tid; i < HID / 2; i += stride)
        reinterpret_cast<uint32_t*>(g_y0h + N_NODES * HID)[i] = 0u;
    for (int i = tid; i < 256 / 2; i += stride)
        reinterpret_cast<uint32_t*>(g_a1h + N_NODES * 256)[i] = 0u;
    if (tid == 0) g_depthmax = 0;
}

// ---------------- K2: degrees (int4 edges), depth max, graph counts ---------------
__global__ void k_stats(const int* __restrict__ edge, const int* __restrict__ depth,
                        const int* __restrict__ batch) {
    int tid = blockIdx.x * blockDim.x + threadIdx.x;
    int stride = gridDim.x * blockDim.x;
    const int4* dst4 = reinterpret_cast<const int4*>(edge + N_EDGES);
    for (int q = tid; q < N_EDGES / 4; q += stride) {
        int4 d = __ldg(&dst4[q]);
        atomicAdd(&g_deg[d.x], 1);
        atomicAdd(&g_deg[d.y], 1);
        atomicAdd(&g_deg[d.z], 1);
        atomicAdd(&g_deg[d.w], 1);
    }
    int dm = 0;
    for (int i = tid; i < N_NODES; i += stride) dm = max(dm, depth[i]);
    dm = __reduce_max_sync(0xffffffffu, dm);
    if ((threadIdx.x & 31) == 0) atomicMax(&g_depthmax, dm);
    for (int i = tid; i < N_NODES; i += stride)
        atomicAdd(&g_cnt[batch[i]], 1.0f);
}

// ---------------- K3a/b: two-level exclusive scan of PADDED degrees ---------------
__global__ void k_scan1() {
    __shared__ int ws[8];
    int b = blockIdx.x, tid = threadIdx.x;
    int lane = tid & 31, wid = tid >> 5;
    int i = b * 256 + tid;
    int v = (i < N_NODES) ? ((g_deg[i] + 7) & ~7) : 0;   // pad to multiple of 8
    int x = v;
#pragma unroll
    for (int o = 1; o < 32; o <<= 1) {
        int y = __shfl_up_sync(0xffffffffu, x, o);
        if (lane >= o) x += y;
    }
    if (lane == 31) ws[wid] = x;
    __syncthreads();
    if (tid < 8) {
        int s = ws[tid];
#pragma unroll
        for (int o = 1; o < 8; o <<= 1) {
            int y = __shfl_up_sync(0xffu, s, o);
            if ((tid & 7) >= o) s += y;
        }
        ws[tid] = s;
    }
    __syncthreads();
    int pre = (wid > 0) ? ws[wid - 1] : 0;
    if (i < N_NODES) g_off[i] = pre + x - v;
    if (tid == 255) g_bsum[b] = pre + x;
}
__global__ void k_scan2() {
    __shared__ int ws[16];
    int tid = threadIdx.x;
    int lane = tid & 31, wid = tid >> 5;
    int v = g_bsum[tid];
    int x = v;
#pragma unroll
    for (int o = 1; o < 32; o <<= 1) {
        int y = __shfl_up_sync(0xffffffffu, x, o);
        if (lane >= o) x += y;
    }
    if (lane == 31) ws[wid] = x;
    __syncthreads();
    if (tid < 16) {
        int s = ws[tid];
#pragma unroll
        for (int o = 1; o < 16; o <<= 1) {
            int y = __shfl_up_sync(0xffffu, s, o);
            if ((tid & 15) >= o) s += y;
        }
        ws[tid] = s;
    }
    __syncthreads();
    int pre = (wid > 0) ? ws[wid - 1] : 0;
    g_bsum[tid] = pre + x - v;
}
// final padded offset of node d = g_off[d] + g_bsum[d >> 8]

// ---------------- K4: pad-fill + bucket edges by destination ----------------------
__global__ void k_sortedges(const int* __restrict__ edge) {
    int tid = blockIdx.x * blockDim.x + threadIdx.x;
    int stride = gridDim.x * blockDim.x;
    for (int d = tid; d < N_NODES; d += stride) {
        int deg = g_deg[d];
        int pdeg = (deg + 7) & ~7;
        int beg = g_off[d] + g_bsum[d >> 8];
        for (int k = deg; k < pdeg; k++) g_ssrc[beg + k] = N_NODES;
    }
    const int4* src4 = reinterpret_cast<const int4*>(edge);
    const int4* dst4 = reinterpret_cast<const int4*>(edge + N_EDGES);
    for (int q = tid; q < N_EDGES / 4; q += stride) {
        int4 s = __ldg(&src4[q]);
        int4 d = __ldg(&dst4[q]);
        int p;
        p = atomicAdd(&g_cursor[d.x], 1);
        g_ssrc[g_off[d.x] + g_bsum[d.x >> 8] + p] = s.x;
        p = atomicAdd(&g_cursor[d.y], 1);
        g_ssrc[g_off[d.y] + g_bsum[d.y >> 8] + p] = s.y;
        p = atomicAdd(&g_cursor[d.z], 1);
        g_ssrc[g_off[d.z] + g_bsum[d.z >> 8] + p] = s.z;
        p = atomicAdd(&g_cursor[d.w], 1);
        g_ssrc[g_off[d.w] + g_bsum[d.w >> 8] + p] = s.w;
    }
}

// ---------------- K5: ident embedding tables (fp16 output) ------------------------
__global__ __launch_bounds__(256) void k_table_id(const float* __restrict__ embi,
                                                  const float* __restrict__ Ws0,
                                                  const float* __restrict__ Wn0) {
    __shared__ float sW[32][128];
    __shared__ float nW[32][128];
    int tid = threadIdx.x;
    for (int i = tid; i < 32 * 128; i += 256) {
        int k = i >> 7, n = i & 127;
        sW[k][n] = Ws0[(64 + k) * 128 + n];
        nW[k][n] = Wn0[(64 + k) * 128 + n];
    }
    __syncthreads();
    int lane = tid & 31;
    int gw = (blockIdx.x * 256 + tid) >> 5;
    int nwarps = (gridDim.x * 256) >> 5;
    for (int r = gw; r < ID_ROWS; r += nwarps) {
        float me = embi[r * 32 + lane];
        unsigned long long as0 = 0, as1 = 0, an0 = 0, an1 = 0;
#pragma unroll
        for (int k = 0; k < 32; k++) {
            float e = __shfl_sync(0xffffffffu, me, k);
            unsigned long long e2 = dup2(e);
            const unsigned long long* ps =
                reinterpret_cast<const unsigned long long*>(&sW[k][lane * 4]);
            const unsigned long long* pn =
                reinterpret_cast<const unsigned long long*>(&nW[k][lane * 4]);
            fma2(as0, e2, ps[0]); fma2(as1, e2, ps[1]);
            fma2(an0, e2, pn[0]); fma2(an1, e2, pn[1]);
        }
        float v0, v1, v2, v3;
        unpack2(as0, v0, v1); unpack2(as1, v2, v3);
        st4h(g_TIs + r * 128 + lane * 4, make_float4(v0, v1, v2, v3));
        unpack2(an0, v0, v1); unpack2(an1, v2, v3);
        st4h(g_TIn + r * 128 + lane * 4, make_float4(v0, v1, v2, v3));
    }
}

// ---------------- K6: node-type tables + weight hi/lo split (fused) ---------------
__global__ void k_table_node(const float* __restrict__ embn,
                             const float* __restrict__ Ws0,
                             const float* __restrict__ Wn0,
                             const float* __restrict__ Ws1,
                             const float* __restrict__ Wn1) {
    int tid = threadIdx.x;
    if (blockIdx.x < 128) {   // weight split part
        int i = blockIdx.x * 256 + tid;
        int r = i >> 7, n = i & 127;
        float v = (r < 128) ? Ws1[r * 128 + n] : Wn1[(r - 128) * 128 + n];
        __half hi = __float2half_rn(v);
        g_w1hi[i] = hi;
        g_w1lo[i] = __float2half_rn(v - __half2float(hi));
        return;
    }
    int lane = tid & 31;
    int gw = ((blockIdx.x - 128) * 256 + tid) >> 5;
    int nwarps = ((gridDim.x - 128) * 256) >> 5;
    for (int r = gw; r < NT_ROWS; r += nwarps) {
        float me0 = embn[r * 64 + lane];
        float me1 = embn[r * 64 + 32 + lane];
        float4 as = make_float4(0, 0, 0, 0), an = make_float4(0, 0, 0, 0);
#pragma unroll
        for (int k = 0; k < 64; k++) {
            float e = (k < 32) ? __shfl_sync(0xffffffffu, me0, k)
                               : __shfl_sync(0xffffffffu, me1, k - 32);
            float4 ws = ld4(Ws0 + k * 128 + lane * 4);
            float4 wn = ld4(Wn0 + k * 128 + lane * 4);
            fma4(as, e, ws);
            fma4(an, e, wn);
        }
        *reinterpret_cast<float4*>(g_TNs + r * 128 + lane * 4) = as;
        *reinterpret_cast<float4*>(g_TNn + r * 128 + lane * 4) = an;
    }
}

// ---------------- K7: per-node transformed features (self0 fp16) ------------------
__global__ void k_nodefeat(const int* __restrict__ nt, const int* __restrict__ ih,
                           const float* __restrict__ flags, const int* __restrict__ depth,
                           const float* __restrict__ Ws0, const float* __restrict__ Wn0) {
    int tid = threadIdx.x;
    int lane = tid & 31;
    int gw = (blockIdx.x * 256 + tid) >> 5;
    int nwarps = (gridDim.x * 256) >> 5;
    float inv_dmax = 1.0f / fmaxf((float)g_depthmax, 1.0f);
    int c4 = lane * 4;
    for (int i = gw; i < N_NODES; i += nwarps) {
        int t = nt[i], id = ih[i];
        float4 s = ld4(g_TNs + t * 128 + c4);
        haccu(s, *reinterpret_cast<const uint2*>(g_TIs + id * 128 + c4));
        float4 y = ld4(g_TNn + t * 128 + c4);
        haccu(y, *reinterpret_cast<const uint2*>(g_TIn + id * 128 + c4));
        float dn = (float)depth[i] * inv_dmax;
#pragma unroll
        for (int j = 0; j < 5; j++) {
            float f = __ldg(&flags[i * 5 + j]);
            fma4(s, f, ld4(Ws0 + (96 + j) * 128 + c4));
            fma4(y, f, ld4(Wn0 + (96 + j) * 128 + c4));
        }
        fma4(s, dn, ld4(Ws0 + 101 * 128 + c4));
        fma4(y, dn, ld4(Wn0 + 101 * 128 + c4));
        st4h(g_self0h + i * 128 + c4, s);
        st4h(g_y0h + i * 128 + c4, y);
        if (lane == 0) g_invdeg[i] = 1.0f / fmaxf((float)g_deg[i], 1.0f);
    }
}

// ---------------- K8: layer-0 aggregation (8 warps/CTA; pipelined) ----------------
__global__ __launch_bounds__(256) void k_agg0(const float* __restrict__ b1,
                                              const float* __restrict__ b2) {
    int tid = threadIdx.x;
    int lane = tid & 31;
    int d = blockIdx.x * 8 + (tid >> 5);
    if (d >= N_NODES) return;
    int c4 = lane * 4;
    int beg = g_off[d] + g_bsum[d >> 8];
    int end = beg + ((g_deg[d] + 7) & ~7);
    float4 a0 = make_float4(0, 0, 0, 0), a1 = a0, a2 = a0, a3 = a0;
    int l8 = lane & 7;
    int sv = (beg < end) ? __ldg(&g_ssrc[beg + l8]) : 0;
    for (int k = beg; k < end; k += 8) {
        int svn = (k + 8 < end) ? __ldg(&g_ssrc[k + 8 + l8]) : 0;
        int s[8];
#pragma unroll
        for (int j = 0; j < 8; j++) s[j] = __shfl_sync(0xffffffffu, sv, j);
        uint2 u[8];
#pragma unroll
        for (int j = 0; j < 8; j++)
            u[j] = *reinterpret_cast<const uint2*>(g_y0h + s[j] * 128 + c4);
        haccu(a0, u[0]); haccu(a1, u[1]); haccu(a2, u[2]); haccu(a3, u[3]);
        haccu(a0, u[4]); haccu(a1, u[5]); haccu(a2, u[6]); haccu(a3, u[7]);
        sv = svn;
    }
    add4(a0, a1); add4(a2, a3); add4(a0, a2);
    float inv = g_invdeg[d];
    float4 v = h2f4(*reinterpret_cast<const uint2*>(g_self0h + d * 128 + c4));
    fma4(v, inv, a0);
    float4 bias1 = __ldg(reinterpret_cast<const float4*>(b1 + c4));
    float4 bias2 = __ldg(reinterpret_cast<const float4*>(b2 + c4));
    v.x = fmaxf(v.x + bias1.x + bias2.x, 0.f);
    v.y = fmaxf(v.y + bias1.y + bias2.y, 0.f);
    v.z = fmaxf(v.z + bias1.z + bias2.z, 0.f);
    v.w = fmaxf(v.w + bias1.w + bias2.w, 0.f);
    st4h(g_a1h + d * 256 + c4, v);
}

// ---------------- K9: layer-1 aggregation (8 warps/CTA; pipelined) ----------------
__global__ __launch_bounds__(256) void k_agg1() {
    int tid = threadIdx.x;
    int lane = tid & 31;
    int d = blockIdx.x * 8 + (tid >> 5);
    if (d >= N_NODES) return;
    int c4 = lane * 4;
    int beg = g_off[d] + g_bsum[d >> 8];
    int end = beg + ((g_deg[d] + 7) & ~7);
    float4 a0 = make_float4(0, 0, 0, 0), a1 = a0, a2 = a0, a3 = a0;
    int l8 = lane & 7;
    int sv = (beg < end) ? __ldg(&g_ssrc[beg + l8]) : 0;
    for (int k = beg; k < end; k += 8) {
        int svn = (k + 8 < end) ? __ldg(&g_ssrc[k + 8 + l8]) : 0;
        int s[8];
#pragma unroll
        for (int j = 0; j < 8; j++) s[j] = __shfl_sync(0xffffffffu, sv, j);
        uint2 u[8];
#pragma unroll
        for (int j = 0; j < 8; j++)
            u[j] = *reinterpret_cast<const uint2*>(g_a1h + s[j] * 256 + c4);
        haccu(a0, u[0]); haccu(a1, u[1]); haccu(a2, u[2]); haccu(a3, u[3]);
        haccu(a0, u[4]); haccu(a1, u[5]); haccu(a2, u[6]); haccu(a3, u[7]);
        sv = svn;
    }
    add4(a0, a1); add4(a2, a3); add4(a0, a2);
    float inv = g_invdeg[d];
    a0.x *= inv; a0.y *= inv; a0.z *= inv; a0.w *= inv;
    st4h(g_a1h + d * 256 + 128 + c4, a0);
}

// ---------------- K10: tensor-core GEMM (B hi/lo split) + bias + relu + pool ------
__global__ __launch_bounds__(256) void k_gemm_h(const float* __restrict__ bs,
                                                const float* __restrict__ bn,
                                                const int* __restrict__ batch) {
    __shared__ __half As[128][48];   // 96B rows (16B-aligned)
    __shared__ __half Bh[32][136];   // 272B rows (16B-aligned)
    __shared__ __half Bl[32][136];
    int tid = threadIdx.x;
    int lane = tid & 31, wid = tid >> 5;
    int wm = wid & 3;
    int wn = wid >> 2;
    int m0 = blockIdx.x * 128;

    float acc[2][8][4];
#pragma unroll
    for (int mi = 0; mi < 2; mi++)
#pragma unroll
        for (int ni = 0; ni < 8; ni++)
#pragma unroll
            for (int q = 0; q < 4; q++) acc[mi][ni][q] = 0.f;

    uint32_t sA = smem_u32(As), sBh = smem_u32(Bh), sBl = smem_u32(Bl);

    for (int kt = 0; kt < 8; kt++) {
        int kk = kt * 32;
#pragma unroll
        for (int i = 0; i < 2; i++) {
            int idx = tid + i * 256;
            int row = idx >> 2, seg = idx & 3;
            uint4 v = make_uint4(0, 0, 0, 0);
            int grow = m0 + row;
            if (grow < N_NODES)
                v = *reinterpret_cast<const uint4*>(g_a1h + grow * 256 + kk + seg * 8);
            *reinterpret_cast<uint4*>(&As[row][seg * 8]) = v;
        }
#pragma unroll
        for (int i = 0; i < 2; i++) {
            int idx = tid + i * 256;
            int row = idx >> 4, seg = idx & 15;
            *reinterpret_cast<uint4*>(&Bh[row][seg * 8]) =
                *reinterpret_cast<const uint4*>(g_w1hi + (kk + row) * 128 + seg * 8);
            *reinterpret_cast<uint4*>(&Bl[row][seg * 8]) =
                *reinterpret_cast<const uint4*>(g_w1lo + (kk + row) * 128 + seg * 8);
        }
        __syncthreads();
#pragma unroll
        for (int ks = 0; ks < 32; ks += 16) {
            uint32_t afr[2][4];
#pragma unroll
            for (int mi = 0; mi < 2; mi++) {
                uint32_t addr = sA + ((wm * 32 + mi * 16 + (lane & 15)) * 48 +
                                      ks + ((lane >> 4) << 3)) * 2;
                LDSM4(afr[mi][0], afr[mi][1], afr[mi][2], afr[mi][3], addr);
            }
            uint32_t bh[8][2], bl[8][2];
#pragma unroll
            for (int nq = 0; nq < 4; nq++) {
                uint32_t off = ((ks + (lane & 7) + ((lane >> 3) & 1) * 8) * 136 +
                                wn * 64 + nq * 16 + ((lane >> 4) & 1) * 8) * 2;
                LDSM4T(bh[nq * 2][0], bh[nq * 2][1], bh[nq * 2 + 1][0],
                       bh[nq * 2 + 1][1], sBh + off);
                LDSM4T(bl[nq * 2][0], bl[nq * 2][1], bl[nq * 2 + 1][0],
                       bl[nq * 2 + 1][1], sBl + off);
            }
#pragma unroll
            for (int mi = 0; mi < 2; mi++)
#pragma unroll
                for (int ni = 0; ni < 8; ni++) {
                    MMA16816(acc[mi][ni], afr[mi], bh[ni][0], bh[ni][1]);
                    MMA16816(acc[mi][ni], afr[mi], bl[ni][0], bl[ni][1]);
                }
        }
        __syncthreads();
    }

    // epilogue: bias + relu + red into pooled
    int tg = lane & 3, rg = lane >> 2;
#pragma unroll
    for (int mi = 0; mi < 2; mi++) {
        int r0 = m0 + wm * 32 + mi * 16 + rg;
        int r1 = r0 + 8;
        int bi0 = (r0 < N_NODES) ? __ldg(&batch[r0]) : -1;
        int bi1 = (r1 < N_NODES) ? __ldg(&batch[r1]) : -1;
#pragma unroll
        for (int ni = 0; ni < 8; ni++) {
            int c = wn * 64 + ni * 8 + tg * 2;
            float bb0 = __ldg(&bs[c]) + __ldg(&bn[c]);
            float bb1 = __ldg(&bs[c + 1]) + __ldg(&bn[c + 1]);
            float* ac = acc[mi][ni];
            if (bi0 >= 0)
                red2(g_pooled + bi0 * 128 + c,
                     fmaxf(ac[0] + bb0, 0.f), fmaxf(ac[1] + bb1, 0.f));
            if (bi1 >= 0)
                red2(g_pooled + bi1 * 128 + c,
                     fmaxf(ac[2] + bb0, 0.f), fmaxf(ac[3] + bb1, 0.f));
        }
    }
}

// ---------------- K11: heads ------------------------------------------------------
__global__ void k_heads(const float* __restrict__ Wr, const float* __restrict__ br,
                        const float* __restrict__ Wc, const float* __restrict__ bc,
                        float* __restrict__ out) {
    int g = blockIdx.x;
    int lane = threadIdx.x;
    float inv = 1.0f / fmaxf(g_cnt[g], 1.0f);
    float4 gv = *reinterpret_cast<const float4*>(g_pooled + g * HID + lane * 4);
    float gvals[4] = {gv.x * inv, gv.y * inv, gv.z * inv, gv.w * inv};

    float pr = 0.f;
#pragma unroll
    for (int i = 0; i < 4; i++) pr += gvals[i] * Wr[lane * 4 + i];
#pragma unroll
    for (int off = 16; off > 0; off >>= 1) pr += __shfl_xor_sync(0xffffffffu, pr, off);
    if (lane == 0) out[g] = pr + br[0];

    for (int o = 0; o < NCAT; o++) {
        float p = 0.f;
#pragma unroll
        for (int i = 0; i < 4; i++) p += gvals[i] * Wc[(lane * 4 + i) * NCAT + o];
#pragma unroll
        for (int off = 16; off > 0; off >>= 1) p += __shfl_xor_sync(0xffffffffu, p, off);
        if (lane == 0) out[N_GRAPHS + g * NCAT + o] = p + bc[o];
    }
}

// ---------------- launch (single stream) ------------------------------------------
extern "C" void kernel_launch(void* const* d_in, const int* in_sizes, int n_in,
                              void* d_out, int out_size) {
    const int*   node_type = (const int*)d_in[0];
    const int*   ident     = (const int*)d_in[1];
    const float* flags     = (const float*)d_in[2];
    const int*   depth     = (const int*)d_in[3];
    const int*   edge      = (const int*)d_in[4];
    const int*   batch     = (const int*)d_in[5];
    const float* emb_node  = (const float*)d_in[6];
    const float* emb_ident = (const float*)d_in[7];
    const float* Ws0 = (const float*)d_in[8];
    const float* bs0 = (const float*)d_in[9];
    const float* Wn0 = (const float*)d_in[10];
    const float* bn0 = (const float*)d_in[11];
    const float* Ws1 = (const float*)d_in[12];
    const float* bs1 = (const float*)d_in[13];
    const float* Wn1 = (const float*)d_in[14];
    const float* bn1 = (const float*)d_in[15];
    const float* Wr  = (const float*)d_in[16];
    const float* br  = (const float*)d_in[17];
    const float* Wc  = (const float*)d_in[18];
    const float* bc  = (const float*)d_in[19];
    float* out = (float*)d_out;

    k_zero<<<1024, 256>>>();
    k_stats<<<2048, 256>>>(edge, depth, batch);
    k_scan1<<<(N_NODES + 255) / 256, 256>>>();
    k_scan2<<<1, 512>>>();
    k_sortedges<<<2048, 256>>>(edge);
    k_table_id<<<2048, 256>>>(emb_ident, Ws0, Wn0);
    k_table_node<<<128 + 33, 256>>>(emb_node, Ws0, Wn0, Ws1, Wn1);
    k_nodefeat<<<2048, 256>>>(node_type, ident, flags, depth, Ws0, Wn0);
    k_agg0<<<(N_NODES + 7) / 8, 256>>>(bs0, bn0);
    k_agg1<<<(N_NODES + 7) / 8, 256>>>();
    k_gemm_h<<<(N_NODES + 127) / 128, 256>>>(bs1, bn1, batch);
    k_heads<<<N_GRAPHS, 32>>>(Wr, br, Wc, bc, out);
}